// round 13
// baseline (speedup 1.0000x reference)
#include <cuda_runtime.h>
#include <cuda_fp16.h>
#include <cstdint>

#define N_NODES 10000
#define N_EDGES 320000
#define IN_F    256
#define HD      512   // NUM_HEADS * OUT_FEATS
#define NH      8

// ---------------- scratch (device globals; zero-initialized at load) -------
__device__ __half g_ah[N_NODES * IN_F];     // feat in fp16
__device__ __half g_bh[IN_F * HD];          // W in fp16
__device__ __half g_fth[N_NODES * HD];      // projected features fp16 [N, 512]
__device__ float  g_wl[IN_F * NH];          // W @ attn_l  [256, 8]
__device__ float  g_wr[IN_F * NH];          // W @ attn_r  [256, 8]
__device__ float  g_el[N_NODES * NH];
__device__ float  g_er[N_NODES * NH];
__device__ int    g_count[10240];           // zeroed by k_scan after use
__device__ int    g_rowstart[N_NODES + 1];
__device__ int    g_woff[N_NODES];
__device__ int    g_srcs[N_EDGES];          // src indices bucketed by dst (CSR)
__device__ float  g_a[N_EDGES * NH];        // normalized attention (incl adj mask)

// ---------------- asm helpers ----------------
__device__ __forceinline__ void ldsm_x4(unsigned* r, unsigned addr) {
    asm volatile("ldmatrix.sync.aligned.m8n8.x4.shared.b16 {%0,%1,%2,%3}, [%4];"
                 : "=r"(r[0]), "=r"(r[1]), "=r"(r[2]), "=r"(r[3]) : "r"(addr));
}
__device__ __forceinline__ void ldsm_x4t(unsigned* r, unsigned addr) {
    asm volatile("ldmatrix.sync.aligned.m8n8.x4.trans.shared.b16 {%0,%1,%2,%3}, [%4];"
                 : "=r"(r[0]), "=r"(r[1]), "=r"(r[2]), "=r"(r[3]) : "r"(addr));
}
__device__ __forceinline__ void mma16816(float* c, const unsigned* a, const unsigned* b) {
    asm volatile("mma.sync.aligned.m16n8k16.row.col.f32.f16.f16.f32 "
                 "{%0,%1,%2,%3}, {%4,%5,%6,%7}, {%8,%9}, {%0,%1,%2,%3};"
                 : "+f"(c[0]), "+f"(c[1]), "+f"(c[2]), "+f"(c[3])
                 : "r"(a[0]), "r"(a[1]), "r"(a[2]), "r"(a[3]), "r"(b[0]), "r"(b[1]));
}
__device__ __forceinline__ void cp16(unsigned saddr, const void* gaddr, int src_bytes) {
    asm volatile("cp.async.cg.shared.global [%0], [%1], 16, %2;"
                 :: "r"(saddr), "l"(gaddr), "r"(src_bytes));
}
#define CP_COMMIT() asm volatile("cp.async.commit_group;" ::: "memory")
#define CP_WAIT1()  asm volatile("cp.async.wait_group 1;" ::: "memory")
#define CP_WAIT0()  asm volatile("cp.async.wait_group 0;" ::: "memory")

// ---------------- 0a: convert feat -> fp16 ----------------
__global__ void k_cvtA(const float4* __restrict__ in) {
    int i = blockIdx.x * blockDim.x + threadIdx.x;   // 8 floats per thread
    if (i < N_NODES * IN_F / 8) {
        float4 a = in[i * 2], b = in[i * 2 + 1];
        __half2 h0 = __floats2half2_rn(a.x, a.y), h1 = __floats2half2_rn(a.z, a.w);
        __half2 h2 = __floats2half2_rn(b.x, b.y), h3 = __floats2half2_rn(b.z, b.w);
        uint4 v = make_uint4(*(unsigned*)&h0, *(unsigned*)&h1,
                             *(unsigned*)&h2, *(unsigned*)&h3);
        ((uint4*)g_ah)[i] = v;
    }
}
// ---------------- 0b: convert W -> fp16 ----------------
__global__ void k_cvtW(const float4* __restrict__ in) {
    int i = blockIdx.x * blockDim.x + threadIdx.x;
    if (i < IN_F * HD / 8) {
        float4 a = in[i * 2], b = in[i * 2 + 1];
        __half2 h0 = __floats2half2_rn(a.x, a.y), h1 = __floats2half2_rn(a.z, a.w);
        __half2 h2 = __floats2half2_rn(b.x, b.y), h3 = __floats2half2_rn(b.z, b.w);
        uint4 v = make_uint4(*(unsigned*)&h0, *(unsigned*)&h1,
                             *(unsigned*)&h2, *(unsigned*)&h3);
        ((uint4*)g_bh)[i] = v;
    }
}

// ---------------- 0c: wl = W@al, wr = W@ar  (warp per k-row) ----------------
__global__ void k_wlr(const float* __restrict__ W, const float* __restrict__ al,
                      const float* __restrict__ ar) {
    int k    = blockIdx.x * 8 + (threadIdx.x >> 5);   // 0..255
    int lane = threadIdx.x & 31;
    const float* wrow = W + (size_t)k * HD;
#pragma unroll
    for (int h = 0; h < NH; h++) {
        float w0 = wrow[h * 64 + lane], w1 = wrow[h * 64 + lane + 32];
        float sl = w0 * al[h * 64 + lane] + w1 * al[h * 64 + lane + 32];
        float sr = w0 * ar[h * 64 + lane] + w1 * ar[h * 64 + lane + 32];
#pragma unroll
        for (int off = 16; off > 0; off >>= 1) {
            sl += __shfl_xor_sync(0xffffffffu, sl, off);
            sr += __shfl_xor_sync(0xffffffffu, sr, off);
        }
        if (lane == 0) { g_wl[k * NH + h] = sl; g_wr[k * NH + h] = sr; }
    }
}

// ---------------- 0d: el/er = feat @ wl/wr  (warp per node, fp32) ----------
__global__ void k_elr(const float* __restrict__ feat) {
    int n    = blockIdx.x * 8 + (threadIdx.x >> 5);
    int lane = threadIdx.x & 31;
    float accl[NH], accr[NH];
#pragma unroll
    for (int h = 0; h < NH; h++) { accl[h] = 0.f; accr[h] = 0.f; }
    const float* fr = feat + (size_t)n * IN_F;
#pragma unroll
    for (int i = 0; i < 8; i++) {
        int k = lane + 32 * i;
        float f = fr[k];
        const float4* wl4 = (const float4*)&g_wl[k * NH];
        const float4* wr4 = (const float4*)&g_wr[k * NH];
        float4 l0 = wl4[0], l1 = wl4[1], r0 = wr4[0], r1 = wr4[1];
        accl[0] += f * l0.x; accl[1] += f * l0.y; accl[2] += f * l0.z; accl[3] += f * l0.w;
        accl[4] += f * l1.x; accl[5] += f * l1.y; accl[6] += f * l1.z; accl[7] += f * l1.w;
        accr[0] += f * r0.x; accr[1] += f * r0.y; accr[2] += f * r0.z; accr[3] += f * r0.w;
        accr[4] += f * r1.x; accr[5] += f * r1.y; accr[6] += f * r1.z; accr[7] += f * r1.w;
    }
    float outl = 0.f, outr = 0.f;
#pragma unroll
    for (int h = 0; h < NH; h++) {
        float sl = accl[h], sr = accr[h];
#pragma unroll
        for (int off = 16; off > 0; off >>= 1) {
            sl += __shfl_xor_sync(0xffffffffu, sl, off);
            sr += __shfl_xor_sync(0xffffffffu, sr, off);
        }
        if (lane == h) { outl = sl; outr = sr; }
    }
    if (lane < NH) {
        g_el[n * NH + lane] = outl;
        g_er[n * NH + lane] = outr;
    }
}

// ---------------- 1: degree histogram (1 thread/edge) ----------------
__global__ void k_hist(const int* __restrict__ dst) {
    int e = blockIdx.x * blockDim.x + threadIdx.x;
    if (e < N_EDGES) atomicAdd(&g_count[dst[e]], 1);
}

// ---------------- 2: exclusive scan (single block) + re-zero counts --------
__global__ void k_scan() {
    __shared__ int sh[10240];
    __shared__ int wsums[32];
    int tid = threadIdx.x, lane = tid & 31, w = tid >> 5;
    int4* sh4 = (int4*)sh;
    int4* gc4 = (int4*)g_count;
    for (int i = tid; i < 2560; i += 1024) sh4[i] = gc4[i];
    __syncthreads();
    const int4 z4 = make_int4(0, 0, 0, 0);
    for (int i = tid; i < 2560; i += 1024) gc4[i] = z4;
    int base = tid * 10;
    int local[10];
    int s = 0;
#pragma unroll
    for (int i = 0; i < 10; i++) { local[i] = s; s += sh[base + i]; }
    int inc = s;
#pragma unroll
    for (int off = 1; off < 32; off <<= 1) {
        int v = __shfl_up_sync(0xffffffffu, inc, off);
        if (lane >= off) inc += v;
    }
    if (lane == 31) wsums[w] = inc;
    __syncthreads();
    if (w == 0) {
        int v = wsums[lane];
        int wi = v;
#pragma unroll
        for (int off = 1; off < 32; off <<= 1) {
            int t = __shfl_up_sync(0xffffffffu, wi, off);
            if (lane >= off) wi += t;
        }
        wsums[lane] = wi - v;   // exclusive
    }
    __syncthreads();
    int excl = wsums[w] + inc - s;
#pragma unroll
    for (int i = 0; i < 10; i++) sh[base + i] = excl + local[i];
    __syncthreads();
    int4* rs4 = (int4*)g_rowstart;
    int4* wo4 = (int4*)g_woff;
    for (int i = tid; i < 2500; i += 1024) { int4 v = sh4[i]; rs4[i] = v; wo4[i] = v; }
    if (tid == 0) g_rowstart[N_NODES] = N_EDGES;
}

// ---------------- 3: scatter edges into CSR buckets (1 thread/edge) --------
__global__ void k_scatter(const int* __restrict__ src, const int* __restrict__ dst) {
    int e = blockIdx.x * blockDim.x + threadIdx.x;
    if (e < N_EDGES) {
        int p = atomicAdd(&g_woff[dst[e]], 1);
        g_srcs[p] = src[e];
    }
}

// ---------------- 4: tensor-core GEMM, cp.async staged, B resident --------
#define ASTRIDE 72
#define B_BYTES (256 * ASTRIDE * 2)     // 36864
#define A_BYTES (128 * ASTRIDE * 2)     // 18432
#define GEMM_SMEM (B_BYTES + 2 * A_BYTES)
__global__ __launch_bounds__(256) void k_gemm() {
    extern __shared__ __half dynsmem[];
    const int bx = blockIdx.x;          // head (0..7)
    const int by = blockIdx.y;          // row tile (0..78)
    const int tid = threadIdx.x;
    const int w = tid >> 5, lane = tid & 31;
    const int row0 = by * 128;

    const unsigned s_b  = (unsigned)__cvta_generic_to_shared(dynsmem);
    const unsigned s_a0 = s_b + B_BYTES;

#pragma unroll
    for (int i = 0; i < 8; i++) {
        int idx = tid + i * 256;
        int k = idx >> 3, c = idx & 7;
        cp16(s_b + k * (ASTRIDE * 2) + c * 16, g_bh + k * HD + bx * 64 + c * 8, 16);
    }
#pragma unroll
    for (int i = 0; i < 4; i++) {
        int idx = tid + i * 256;
        int r = idx >> 3, c = idx & 7;
        int grow = row0 + r;
        int ok = grow < N_NODES ? 16 : 0;
        int gsafe = grow < N_NODES ? grow : (N_NODES - 1);
        cp16(s_a0 + r * (ASTRIDE * 2) + c * 16,
             g_ah + (size_t)gsafe * IN_F + c * 8, ok);
    }
    CP_COMMIT();   // group 0: B + A0
#pragma unroll
    for (int i = 0; i < 4; i++) {
        int idx = tid + i * 256;
        int r = idx >> 3, c = idx & 7;
        int grow = row0 + r;
        int ok = grow < N_NODES ? 16 : 0;
        int gsafe = grow < N_NODES ? grow : (N_NODES - 1);
        cp16(s_a0 + A_BYTES + r * (ASTRIDE * 2) + c * 16,
             g_ah + (size_t)gsafe * IN_F + 64 + c * 8, ok);
    }
    CP_COMMIT();   // group 1: A1

    float acc[8][4];
#pragma unroll
    for (int i = 0; i < 8; i++)
#pragma unroll
        for (int j = 0; j < 4; j++) acc[i][j] = 0.f;

    const int r15 = lane & 15, c8 = (lane >> 4) * 8;

#pragma unroll
    for (int kc = 0; kc < 4; kc++) {
        if (kc < 3) { CP_WAIT1(); } else { CP_WAIT0(); }
        __syncthreads();
        const unsigned a_base = s_a0 + (kc & 1) * A_BYTES
                              + (unsigned)(((w * 16 + r15) * ASTRIDE + c8) * 2);
        const unsigned b_base = s_b + (unsigned)(((kc * 64 + r15) * ASTRIDE + c8) * 2);
#pragma unroll
        for (int ks = 0; ks < 4; ks++) {
            unsigned af[4];
            ldsm_x4(af, a_base + ks * 32);
#pragma unroll
            for (int nb = 0; nb < 4; nb++) {
                unsigned bf[4];
                ldsm_x4t(bf, b_base + (unsigned)(ks * 16 * ASTRIDE * 2) + nb * 32);
                mma16816(acc[nb * 2],     af, bf);
                mma16816(acc[nb * 2 + 1], af, bf + 2);
            }
        }
        if (kc < 2) {
            __syncthreads();
#pragma unroll
            for (int i = 0; i < 4; i++) {
                int idx = tid + i * 256;
                int r = idx >> 3, c = idx & 7;
                int grow = row0 + r;
                int ok = grow < N_NODES ? 16 : 0;
                int gsafe = grow < N_NODES ? grow : (N_NODES - 1);
                cp16(s_a0 + (kc & 1) * A_BYTES + r * (ASTRIDE * 2) + c * 16,
                     g_ah + (size_t)gsafe * IN_F + (kc + 2) * 64 + c * 8, ok);
            }
            CP_COMMIT();
        }
    }

    // epilogue: fp16 ft store only (el/er handled by k_elr)
    const int g = lane >> 2, tg = lane & 3;
    const int rr0 = row0 + w * 16 + g;
    const int rr1 = rr0 + 8;
    if (rr0 < N_NODES) {
        __half* fo = &g_fth[(long long)rr0 * HD + bx * 64 + tg * 2];
#pragma unroll
        for (int na = 0; na < 8; na++)
            *(__half2*)(fo + na * 8) = __floats2half2_rn(acc[na][0], acc[na][1]);
    }
    if (rr1 < N_NODES) {
        __half* fo = &g_fth[(long long)rr1 * HD + bx * 64 + tg * 2];
#pragma unroll
        for (int na = 0; na < 8; na++)
            *(__half2*)(fo + na * 8) = __floats2half2_rn(acc[na][2], acc[na][3]);
    }
}

// ---------------- 5: softmax stats + normalized attention (warp per dst) ---
__global__ void k_soft(const float* __restrict__ adj, const int* __restrict__ idxp) {
    int d    = blockIdx.x * 8 + (threadIdx.x >> 5);
    int lane = threadIdx.x & 31;
    int s0 = g_rowstart[d], s1 = g_rowstart[d + 1];
    if (s1 <= s0) return;

    int idx = *idxp;
    int h   = lane & 7;
    int sub = lane >> 3;
    float er_h = g_er[d * NH + h];

    float m = -1e30f, ssum = 0.f;
    for (int j = s0 + sub; j < s1; j += 4) {
        int s = g_srcs[j];
        float e = g_el[s * NH + h] + er_h;
        e = e > 0.f ? e : 0.2f * e;
        if (e > m) { ssum *= __expf(m - e); m = e; }
        ssum += __expf(e - m);
    }
#pragma unroll
    for (int off = 8; off <= 16; off <<= 1) {
        float mo = __shfl_xor_sync(0xffffffffu, m, off);
        float so = __shfl_xor_sync(0xffffffffu, ssum, off);
        float mn = fmaxf(m, mo);
        ssum = ssum * __expf(m - mn) + so * __expf(mo - mn);
        m = mn;
    }
    float inv = __frcp_rn(ssum);

    const long long adjbase = (long long)idx * N_NODES + (long long)d + idx;
    for (int j = s0 + sub; j < s1; j += 4) {
        int s = g_srcs[j];
        float e = g_el[s * NH + h] + er_h;
        e = e > 0.f ? e : 0.2f * e;
        float wadj = __ldg(&adj[(long long)s * N_NODES + adjbase]);
        g_a[j * NH + h] = __expf(e - m) * inv * wadj;
    }
}

// ---------------- 6: aggregation (warp per dst, single lean pass) ----------
__global__ void k_agg(float* __restrict__ out) {
    int d    = blockIdx.x * 8 + (threadIdx.x >> 5);
    int lane = threadIdx.x & 31;
    int s0 = g_rowstart[d], s1 = g_rowstart[d + 1];

    float acc0[8], acc1[8];
#pragma unroll
    for (int t = 0; t < 8; t++) { acc0[t] = 0.f; acc1[t] = 0.f; }

    const int q0 = lane >> 3;
    const int q1 = 4 + (lane >> 3);
#pragma unroll 4
    for (int j = s0; j < s1; j++) {
        int s = g_srcs[j];
        float a0 = __ldg(&g_a[j * NH + q0]);
        float a1 = __ldg(&g_a[j * NH + q1]);
        const uint4* fh = (const uint4*)&g_fth[(long long)s * HD];
        uint4 u0 = __ldg(&fh[lane]);
        uint4 u1 = __ldg(&fh[lane + 32]);
        {
            const __half2* hp = (const __half2*)&u0;
#pragma unroll
            for (int t = 0; t < 4; t++) {
                float2 f = __half22float2(hp[t]);
                acc0[2 * t]     += a0 * f.x;
                acc0[2 * t + 1] += a0 * f.y;
            }
        }
        {
            const __half2* hp = (const __half2*)&u1;
#pragma unroll
            for (int t = 0; t < 4; t++) {
                float2 f = __half22float2(hp[t]);
                acc1[2 * t]     += a1 * f.x;
                acc1[2 * t + 1] += a1 * f.y;
            }
        }
    }
    float* o = out + (long long)d * HD;
    *(float4*)&o[lane * 8]           = make_float4(acc0[0], acc0[1], acc0[2], acc0[3]);
    *(float4*)&o[lane * 8 + 4]       = make_float4(acc0[4], acc0[5], acc0[6], acc0[7]);
    *(float4*)&o[256 + lane * 8]     = make_float4(acc1[0], acc1[1], acc1[2], acc1[3]);
    *(float4*)&o[256 + lane * 8 + 4] = make_float4(acc1[4], acc1[5], acc1[6], acc1[7]);
}

// ---------------- streams + gemm smem attr (static init; no device mem) ----
static cudaStream_t g_s2, g_s3;
static cudaEvent_t  g_evA, g_evE, g_evS;
namespace {
struct StreamInit {
    StreamInit() {
        cudaStreamCreateWithFlags(&g_s2, cudaStreamNonBlocking);
        cudaStreamCreateWithFlags(&g_s3, cudaStreamNonBlocking);
        cudaEventCreateWithFlags(&g_evA, cudaEventDisableTiming);
        cudaEventCreateWithFlags(&g_evE, cudaEventDisableTiming);
        cudaEventCreateWithFlags(&g_evS, cudaEventDisableTiming);
        cudaFuncSetAttribute(k_gemm, cudaFuncAttributeMaxDynamicSharedMemorySize,
                             GEMM_SMEM);
    }
};
StreamInit s_streamInit;
}

// ---------------- launch ----------------
extern "C" void kernel_launch(void* const* d_in, const int* in_sizes, int n_in,
                              void* d_out, int out_size) {
    const float* feat = (const float*)d_in[0];
    const float* W    = (const float*)d_in[1];
    const float* al   = (const float*)d_in[2];
    const float* ar   = (const float*)d_in[3];
    const float* adj  = (const float*)d_in[4];
    const int*   src  = (const int*)d_in[5];
    const int*   dst  = (const int*)d_in[6];
    const int*   idxp = (const int*)d_in[7];
    float* out = (float*)d_out;

    // fork from capture-origin stream
    cudaEventRecord(g_evA, 0);
    cudaStreamWaitEvent(g_s2, g_evA, 0);
    cudaStreamWaitEvent(g_s3, g_evA, 0);

    k_cvtA<<<1250, 256>>>((const float4*)feat);                    // 1 (def)
    k_cvtW<<<64, 256>>>((const float4*)W);                         // 2 (def)
    k_hist<<<(N_EDGES + 255) / 256, 256, 0, g_s2>>>(dst);          // 3 (s2)
    dim3 ggrid(NH, (N_NODES + 127) / 128);
    k_gemm<<<ggrid, 256, GEMM_SMEM>>>();                           // 4 (def, profiled)

    k_wlr<<<32, 256, 0, g_s3>>>(W, al, ar);                        // 5 (s3)
    k_elr<<<1250, 256, 0, g_s3>>>(feat);                           // 6 (s3)
    cudaEventRecord(g_evE, g_s3);

    k_scan<<<1, 1024, 0, g_s2>>>();                                // 7 (s2)
    k_scatter<<<(N_EDGES + 255) / 256, 256, 0, g_s2>>>(src, dst);  // 8 (s2)
    cudaStreamWaitEvent(g_s2, g_evE, 0);                           // soft needs el/er
    k_soft<<<N_NODES / 8, 256, 0, g_s2>>>(adj, idxp);              // 9 (s2)
    cudaEventRecord(g_evS, g_s2);

    // join: agg needs ft (def) + attention (s2)
    cudaStreamWaitEvent(0, g_evS, 0);
    k_agg<<<N_NODES / 8, 256>>>(out);                              // 10 (def)
}